// round 9
// baseline (speedup 1.0000x reference)
#include <cuda_runtime.h>
#include <cstdint>

// HashEmbedder: Instant-NGP multiresolution hash grid encoding.
// R9: drop the 2-stage software pipeline (it cost 64 regs -> occ 45%,
// leaving L1tex at 78% of peak); plain per-level loop at full occupancy.
// L1 wavefront throughput is fed by warps, not per-thread MLP (R1: occ 83%
// -> L1 86.6% util). Keeps: Morton sort, atomic-free scatter, fused
// scan-reset, exact multiplies, SM-affinity block remap.

#define MAXPTS    524288
#define NBINS_DIM 32
#define NBINS     (NBINS_DIM * NBINS_DIM * NBINS_DIM)   // 32768 = 2^15
#define N_LEVELS  16
#define TABLE_SZ  (1u << 19)
#define TMASK     (TABLE_SZ - 1u)
#define NSM       148

// scratch (allocations forbidden); zero-initialized at module load
__device__ unsigned g_count[NBINS];
__device__ unsigned g_offset[NBINS];
__device__ unsigned g_binrank[MAXPTS];  // bin (15b) | rank<<15
__device__ float4   g_sorted[MAXPTS];   // xyz + original index (int bits)

// res/2 = 0.5*floor(16*cbrt(2)^i): all exactly representable in fp32
__device__ __constant__ float c_resh[N_LEVELS] = {
    8.f, 10.f, 12.5f, 16.f, 20.f, 25.f, 32.f, 40.f,
    50.5f, 64.f, 80.5f, 101.5f, 128.f, 161.f, 203.f, 256.f
};

__device__ __forceinline__ unsigned part1by2(unsigned x) {
    x &= 0x3FF;
    x = (x | (x << 16)) & 0x030000FF;
    x = (x | (x << 8))  & 0x0300F00F;
    x = (x | (x << 4))  & 0x030C30C3;
    x = (x | (x << 2))  & 0x09249249;
    return x;
}

__device__ __forceinline__ unsigned bin_of(float x, float y, float z) {
    int cx = (int)((x + 1.0f) * 16.0f);
    int cy = (int)((y + 1.0f) * 16.0f);
    int cz = (int)((z + 1.0f) * 16.0f);
    cx = min(max(cx, 0), 31);
    cy = min(max(cy, 0), 31);
    cz = min(max(cz, 0), 31);
    return part1by2((unsigned)cx) | (part1by2((unsigned)cy) << 1) |
           (part1by2((unsigned)cz) << 2);
}

// histogram + capture per-point rank from the atomic's return value
__global__ void count_kernel(const float* __restrict__ pts, int n) {
    int i = blockIdx.x * blockDim.x + threadIdx.x;
    if (i >= n) return;
    float x = pts[3 * i + 0], y = pts[3 * i + 1], z = pts[3 * i + 2];
    unsigned b = bin_of(x, y, z);
    unsigned rank = atomicAdd(&g_count[b], 1u);
    g_binrank[i] = b | (rank << 15);
}

// single-block exclusive scan over 32768 bins; also resets g_count to 0
// so the next call/replay starts clean (no separate zero kernel).
__global__ __launch_bounds__(1024)
void scan_kernel() {
    __shared__ unsigned sh[1024];
    int t = threadIdx.x;
    unsigned v[32];
    unsigned s = 0;
#pragma unroll
    for (int i = 0; i < 32; i++) { v[i] = g_count[t * 32 + i]; s += v[i]; }
#pragma unroll
    for (int i = 0; i < 32; i++) g_count[t * 32 + i] = 0;   // reset for next call
    sh[t] = s;
    __syncthreads();
    for (int d = 1; d < 1024; d <<= 1) {
        unsigned x = (t >= d) ? sh[t - d] : 0u;
        __syncthreads();
        sh[t] += x;
        __syncthreads();
    }
    unsigned run = sh[t] - s;
#pragma unroll
    for (int i = 0; i < 32; i++) { g_offset[t * 32 + i] = run; run += v[i]; }
}

// atomic-free scatter: pos = offset[bin] + rank
__global__ void scatter_kernel(const float* __restrict__ pts, int n) {
    int i = blockIdx.x * blockDim.x + threadIdx.x;
    if (i >= n) return;
    unsigned br = g_binrank[i];
    unsigned pos = g_offset[br & 0x7FFFu] + (br >> 15);
    float x = pts[3 * i + 0], y = pts[3 * i + 1], z = pts[3 * i + 2];
    g_sorted[pos] = make_float4(x, y, z, __int_as_float(i));
}

__device__ __forceinline__ float2 lerp2(float2 a, float2 b, float t) {
    float2 r;
    r.x = a.x + t * (b.x - a.x);
    r.y = a.y + t * (b.y - a.y);
    return r;
}

__global__ __launch_bounds__(256)
void hashgrid_kernel(const float2* __restrict__ tables,
                     float4* __restrict__ out,   // [n, 8] float4
                     int n)
{
    // SM-affinity remap: classic launch puts bid -> SM via LUT[bid % 148].
    // Give blocks that share an SM consecutive sorted segments so the SM's
    // resident corner working set is one contiguous Morton region.
    int G = gridDim.x;
    int b = blockIdx.x;
    int g = b % NSM;
    int i = b / NSM;
    int q = G / NSM, r = G % NSM;
    int seg = g * q + min(g, r) + i;

    int s = seg * (int)blockDim.x + threadIdx.x;
    if (s >= n) return;

    float4 f = g_sorted[s];
    int orig = __float_as_int(f.w);

    float ax = f.x + 1.0f;
    float ay = f.y + 1.0f;
    float az = f.z + 1.0f;

    const unsigned P0 = 73856093u, P1 = 19349663u, P2 = 83492791u;

    float4* o = out + (size_t)orig * (N_LEVELS / 2);
    float4 acc;

#pragma unroll
    for (int l = 0; l < N_LEVELS; l++) {
        // scaled = (p+1) * (res/2); res/2 exact -> <=1ulp vs reference
        float rh = c_resh[l];
        float sx = ax * rh, sy = ay * rh, sz = az * rh;

        int ixi = __float2int_rd(sx);
        int iyi = __float2int_rd(sy);
        int izi = __float2int_rd(sz);
        float wx = sx - (float)ixi;
        float wy = sy - (float)iyi;
        float wz = sz - (float)izi;

        unsigned hx0 = (unsigned)ixi * P0, hx1 = hx0 + P0;
        unsigned hy0 = (unsigned)iyi * P1, hy1 = hy0 + P1;
        unsigned hz0 = (unsigned)izi * P2, hz1 = hz0 + P2;

        const float2* t = tables + (size_t)l * TABLE_SZ;

        float2 c000 = __ldg(t + ((hx0 ^ hy0 ^ hz0) & TMASK));
        float2 c001 = __ldg(t + ((hx0 ^ hy0 ^ hz1) & TMASK));
        float2 c010 = __ldg(t + ((hx0 ^ hy1 ^ hz0) & TMASK));
        float2 c011 = __ldg(t + ((hx0 ^ hy1 ^ hz1) & TMASK));
        float2 c100 = __ldg(t + ((hx1 ^ hy0 ^ hz0) & TMASK));
        float2 c101 = __ldg(t + ((hx1 ^ hy0 ^ hz1) & TMASK));
        float2 c110 = __ldg(t + ((hx1 ^ hy1 ^ hz0) & TMASK));
        float2 c111 = __ldg(t + ((hx1 ^ hy1 ^ hz1) & TMASK));

        float2 c00 = lerp2(c000, c001, wz);
        float2 c01 = lerp2(c010, c011, wz);
        float2 c10 = lerp2(c100, c101, wz);
        float2 c11 = lerp2(c110, c111, wz);
        float2 c0  = lerp2(c00, c01, wy);
        float2 c1  = lerp2(c10, c11, wy);
        float2 r2  = lerp2(c0, c1, wx);

        if ((l & 1) == 0) {
            acc.x = r2.x; acc.y = r2.y;
        } else {
            acc.z = r2.x; acc.w = r2.y;
            o[l >> 1] = acc;
        }
    }
}

extern "C" void kernel_launch(void* const* d_in, const int* in_sizes, int n_in,
                              void* d_out, int out_size)
{
    const float*  pts    = (const float*)d_in[0];   // [n, 3]
    const float2* tables = (const float2*)d_in[1];  // [16, 2^19] float2
    float4*       out    = (float4*)d_out;          // [n, 8] float4

    int n = in_sizes[0] / 3;
    if (n > MAXPTS) n = MAXPTS;

    int T = 256;
    int gp = (n + T - 1) / T;

    count_kernel<<<gp, T>>>(pts, n);
    scan_kernel<<<1, 1024>>>();
    scatter_kernel<<<gp, T>>>(pts, n);
    hashgrid_kernel<<<gp, T>>>(tables, out, n);
}

// round 10
// speedup vs baseline: 1.4132x; 1.4132x over previous
#include <cuda_runtime.h>
#include <cstdint>

// HashEmbedder: Instant-NGP multiresolution hash grid encoding.
// R10:
//  - hashgrid restored to R8's pipelined form (measured 158us; R9 proved
//    per-thread MLP > occupancy for feeding L1tex on this kernel).
//  - single-block scan (est. 30-45us, one SM, uncoalesced) replaced by a
//    3-stage parallel scan: 256-block chunk-local scan (+count reset),
//    tiny 256-wide global scan of chunk totals, scatter adds the two.
// Keeps: Morton sort, atomic-free scatter, exact multiplies, SM-affinity
// block remap, __launch_bounds__(256,4).

#define MAXPTS    524288
#define NBINS_DIM 32
#define NBINS     (NBINS_DIM * NBINS_DIM * NBINS_DIM)   // 32768 = 2^15
#define CHUNK     128
#define NCHUNKS   (NBINS / CHUNK)                        // 256
#define N_LEVELS  16
#define TABLE_SZ  (1u << 19)
#define TMASK     (TABLE_SZ - 1u)
#define NSM       148

// scratch (allocations forbidden); zero-initialized at module load
__device__ unsigned g_count[NBINS];
__device__ unsigned g_local[NBINS];     // exclusive prefix within chunk
__device__ unsigned g_partial[NCHUNKS]; // per-chunk totals
__device__ unsigned g_base[NCHUNKS];    // exclusive scan of chunk totals
__device__ unsigned g_binrank[MAXPTS];  // bin (15b) | rank<<15
__device__ float4   g_sorted[MAXPTS];   // xyz + original index (int bits)

// res/2 = 0.5*floor(16*cbrt(2)^i): all exactly representable in fp32
__device__ __constant__ float c_resh[N_LEVELS] = {
    8.f, 10.f, 12.5f, 16.f, 20.f, 25.f, 32.f, 40.f,
    50.5f, 64.f, 80.5f, 101.5f, 128.f, 161.f, 203.f, 256.f
};

__device__ __forceinline__ unsigned part1by2(unsigned x) {
    x &= 0x3FF;
    x = (x | (x << 16)) & 0x030000FF;
    x = (x | (x << 8))  & 0x0300F00F;
    x = (x | (x << 4))  & 0x030C30C3;
    x = (x | (x << 2))  & 0x09249249;
    return x;
}

__device__ __forceinline__ unsigned bin_of(float x, float y, float z) {
    int cx = (int)((x + 1.0f) * 16.0f);
    int cy = (int)((y + 1.0f) * 16.0f);
    int cz = (int)((z + 1.0f) * 16.0f);
    cx = min(max(cx, 0), 31);
    cy = min(max(cy, 0), 31);
    cz = min(max(cz, 0), 31);
    return part1by2((unsigned)cx) | (part1by2((unsigned)cy) << 1) |
           (part1by2((unsigned)cz) << 2);
}

// histogram + capture per-point rank from the atomic's return value
__global__ void count_kernel(const float* __restrict__ pts, int n) {
    int i = blockIdx.x * blockDim.x + threadIdx.x;
    if (i >= n) return;
    float x = pts[3 * i + 0], y = pts[3 * i + 1], z = pts[3 * i + 2];
    unsigned b = bin_of(x, y, z);
    unsigned rank = atomicAdd(&g_count[b], 1u);
    g_binrank[i] = b | (rank << 15);
}

// stage 1: per-chunk exclusive scan (256 blocks x 128 threads, 1 bin/thread),
// writes chunk totals; resets g_count for the next graph replay.
__global__ __launch_bounds__(CHUNK)
void scan_local_kernel() {
    __shared__ unsigned sh[CHUNK];
    int bin = blockIdx.x * CHUNK + threadIdx.x;
    int t = threadIdx.x;
    unsigned v = g_count[bin];
    g_count[bin] = 0;                    // reset for next call
    sh[t] = v;
    __syncthreads();
#pragma unroll
    for (int d = 1; d < CHUNK; d <<= 1) {
        unsigned x = (t >= d) ? sh[t - d] : 0u;
        __syncthreads();
        sh[t] += x;
        __syncthreads();
    }
    g_local[bin] = sh[t] - v;            // exclusive within chunk
    if (t == CHUNK - 1) g_partial[blockIdx.x] = sh[t];
}

// stage 2: exclusive scan of the 256 chunk totals (single tiny block)
__global__ __launch_bounds__(NCHUNKS)
void scan_global_kernel() {
    __shared__ unsigned sh[NCHUNKS];
    int t = threadIdx.x;
    unsigned v = g_partial[t];
    sh[t] = v;
    __syncthreads();
#pragma unroll
    for (int d = 1; d < NCHUNKS; d <<= 1) {
        unsigned x = (t >= d) ? sh[t - d] : 0u;
        __syncthreads();
        sh[t] += x;
        __syncthreads();
    }
    g_base[t] = sh[t] - v;
}

// atomic-free scatter: pos = base[chunk] + local[bin] + rank
__global__ void scatter_kernel(const float* __restrict__ pts, int n) {
    int i = blockIdx.x * blockDim.x + threadIdx.x;
    if (i >= n) return;
    unsigned br = g_binrank[i];
    unsigned bin = br & 0x7FFFu;
    unsigned pos = g_base[bin >> 7] + g_local[bin] + (br >> 15);
    float x = pts[3 * i + 0], y = pts[3 * i + 1], z = pts[3 * i + 2];
    g_sorted[pos] = make_float4(x, y, z, __int_as_float(i));
}

__device__ __forceinline__ float2 lerp2(float2 a, float2 b, float t) {
    float2 r;
    r.x = a.x + t * (b.x - a.x);
    r.y = a.y + t * (b.y - a.y);
    return r;
}

// issue the 8 corner gathers + weights for level `lv` into buffer `buf`
#define LOAD_LEVEL(lv, buf)                                                  \
    do {                                                                     \
        float rh = c_resh[lv];                                               \
        float sx = ax * rh, sy = ay * rh, sz = az * rh;                      \
        int ixi = __float2int_rd(sx);                                        \
        int iyi = __float2int_rd(sy);                                        \
        int izi = __float2int_rd(sz);                                        \
        wbx[buf] = sx - (float)ixi;                                          \
        wby[buf] = sy - (float)iyi;                                          \
        wbz[buf] = sz - (float)izi;                                          \
        unsigned hx0 = (unsigned)ixi * P0, hx1 = hx0 + P0;                   \
        unsigned hy0 = (unsigned)iyi * P1, hy1 = hy0 + P1;                   \
        unsigned hz0 = (unsigned)izi * P2, hz1 = hz0 + P2;                   \
        const float2* t = tables + (size_t)(lv) * TABLE_SZ;                  \
        cbuf[buf][0] = __ldg(t + ((hx0 ^ hy0 ^ hz0) & TMASK));               \
        cbuf[buf][1] = __ldg(t + ((hx0 ^ hy0 ^ hz1) & TMASK));               \
        cbuf[buf][2] = __ldg(t + ((hx0 ^ hy1 ^ hz0) & TMASK));               \
        cbuf[buf][3] = __ldg(t + ((hx0 ^ hy1 ^ hz1) & TMASK));               \
        cbuf[buf][4] = __ldg(t + ((hx1 ^ hy0 ^ hz0) & TMASK));               \
        cbuf[buf][5] = __ldg(t + ((hx1 ^ hy0 ^ hz1) & TMASK));               \
        cbuf[buf][6] = __ldg(t + ((hx1 ^ hy1 ^ hz0) & TMASK));               \
        cbuf[buf][7] = __ldg(t + ((hx1 ^ hy1 ^ hz1) & TMASK));               \
    } while (0)

__global__ __launch_bounds__(256, 4)
void hashgrid_kernel(const float2* __restrict__ tables,
                     float4* __restrict__ out,   // [n, 8] float4
                     int n)
{
    // SM-affinity remap: blocks sharing an SM (bid % 148) get consecutive
    // sorted segments -> each SM's corner working set is one Morton region.
    int G = gridDim.x;
    int b = blockIdx.x;
    int g = b % NSM;
    int i = b / NSM;
    int q = G / NSM, r = G % NSM;
    int seg = g * q + min(g, r) + i;

    int s = seg * (int)blockDim.x + threadIdx.x;
    if (s >= n) return;

    float4 f = g_sorted[s];
    int orig = __float_as_int(f.w);

    float ax = f.x + 1.0f;
    float ay = f.y + 1.0f;
    float az = f.z + 1.0f;

    const unsigned P0 = 73856093u, P1 = 19349663u, P2 = 83492791u;

    float2 cbuf[2][8];
    float wbx[2], wby[2], wbz[2];

    LOAD_LEVEL(0, 0);   // prologue: level 0 in flight

    float4* o = out + (size_t)orig * (N_LEVELS / 2);
    float4 acc;

#pragma unroll
    for (int l = 0; l < N_LEVELS; l++) {
        const int cur = l & 1;
        const int nxt = cur ^ 1;

        // issue next level's gathers BEFORE consuming this level's corners
        if (l + 1 < N_LEVELS) LOAD_LEVEL(l + 1, nxt);

        float wx = wbx[cur], wy = wby[cur], wz = wbz[cur];
        float2 c00 = lerp2(cbuf[cur][0], cbuf[cur][1], wz);
        float2 c01 = lerp2(cbuf[cur][2], cbuf[cur][3], wz);
        float2 c10 = lerp2(cbuf[cur][4], cbuf[cur][5], wz);
        float2 c11 = lerp2(cbuf[cur][6], cbuf[cur][7], wz);
        float2 c0  = lerp2(c00, c01, wy);
        float2 c1  = lerp2(c10, c11, wy);
        float2 r2  = lerp2(c0, c1, wx);

        if ((l & 1) == 0) {
            acc.x = r2.x; acc.y = r2.y;
        } else {
            acc.z = r2.x; acc.w = r2.y;
            o[l >> 1] = acc;
        }
    }
}

extern "C" void kernel_launch(void* const* d_in, const int* in_sizes, int n_in,
                              void* d_out, int out_size)
{
    const float*  pts    = (const float*)d_in[0];   // [n, 3]
    const float2* tables = (const float2*)d_in[1];  // [16, 2^19] float2
    float4*       out    = (float4*)d_out;          // [n, 8] float4

    int n = in_sizes[0] / 3;
    if (n > MAXPTS) n = MAXPTS;

    int T = 256;
    int gp = (n + T - 1) / T;

    count_kernel<<<gp, T>>>(pts, n);
    scan_local_kernel<<<NCHUNKS, CHUNK>>>();
    scan_global_kernel<<<1, NCHUNKS>>>();
    scatter_kernel<<<gp, T>>>(pts, n);
    hashgrid_kernel<<<gp, T>>>(tables, out, n);
}

// round 11
// speedup vs baseline: 1.4262x; 1.0092x over previous
#include <cuda_runtime.h>
#include <cstdint>

// HashEmbedder: Instant-NGP multiresolution hash grid encoding.
// R11:
//  - fine levels (>=11, corner footprint 8-33MB, zero L1 reuse) gather via
//    __ldcg so they stop evicting mid-level corner lines from L1; coarse/mid
//    keep __ldg. Fine-level replay cost is floor-bound either way.
//  - scan_global fused into scan_local via decoupled last-block (atomic
//    ticket, reset each call for graph replay): one fewer launch.
// Keeps: Morton sort, atomic-free scatter, parallel chunk scan, exact
// multiplies, SM-affinity remap, 2-stage pipelined hashgrid (256,4).

#define MAXPTS    524288
#define NBINS_DIM 32
#define NBINS     (NBINS_DIM * NBINS_DIM * NBINS_DIM)   // 32768 = 2^15
#define CHUNK     128
#define NCHUNKS   (NBINS / CHUNK)                        // 256
#define N_LEVELS  16
#define TABLE_SZ  (1u << 19)
#define TMASK     (TABLE_SZ - 1u)
#define NSM       148
#define CG_FROM   11   // levels >= this use __ldcg (L2-only)

// scratch (allocations forbidden); zero-initialized at module load
__device__ unsigned g_count[NBINS];
__device__ unsigned g_local[NBINS];     // exclusive prefix within chunk
__device__ unsigned g_partial[NCHUNKS]; // per-chunk totals
__device__ unsigned g_base[NCHUNKS];    // exclusive scan of chunk totals
__device__ unsigned g_arrive;           // decoupled-scan arrival ticket
__device__ unsigned g_binrank[MAXPTS];  // bin (15b) | rank<<15
__device__ float4   g_sorted[MAXPTS];   // xyz + original index (int bits)

// res/2 = 0.5*floor(16*cbrt(2)^i): all exactly representable in fp32
__device__ __constant__ float c_resh[N_LEVELS] = {
    8.f, 10.f, 12.5f, 16.f, 20.f, 25.f, 32.f, 40.f,
    50.5f, 64.f, 80.5f, 101.5f, 128.f, 161.f, 203.f, 256.f
};

__device__ __forceinline__ unsigned part1by2(unsigned x) {
    x &= 0x3FF;
    x = (x | (x << 16)) & 0x030000FF;
    x = (x | (x << 8))  & 0x0300F00F;
    x = (x | (x << 4))  & 0x030C30C3;
    x = (x | (x << 2))  & 0x09249249;
    return x;
}

__device__ __forceinline__ unsigned bin_of(float x, float y, float z) {
    int cx = (int)((x + 1.0f) * 16.0f);
    int cy = (int)((y + 1.0f) * 16.0f);
    int cz = (int)((z + 1.0f) * 16.0f);
    cx = min(max(cx, 0), 31);
    cy = min(max(cy, 0), 31);
    cz = min(max(cz, 0), 31);
    return part1by2((unsigned)cx) | (part1by2((unsigned)cy) << 1) |
           (part1by2((unsigned)cz) << 2);
}

// histogram + capture per-point rank from the atomic's return value
__global__ void count_kernel(const float* __restrict__ pts, int n) {
    int i = blockIdx.x * blockDim.x + threadIdx.x;
    if (i >= n) return;
    float x = pts[3 * i + 0], y = pts[3 * i + 1], z = pts[3 * i + 2];
    unsigned b = bin_of(x, y, z);
    unsigned rank = atomicAdd(&g_count[b], 1u);
    g_binrank[i] = b | (rank << 15);
}

// per-chunk exclusive scan (256 blocks x 128 threads, 1 bin/thread);
// last-arriving block also scans the 256 chunk totals into g_base.
// Resets g_count and g_arrive so each call/replay starts clean.
__global__ __launch_bounds__(CHUNK)
void scan_kernel() {
    __shared__ unsigned sh[CHUNK];
    __shared__ bool is_last;
    int bin = blockIdx.x * CHUNK + threadIdx.x;
    int t = threadIdx.x;

    unsigned v = g_count[bin];
    g_count[bin] = 0;                    // reset for next call
    sh[t] = v;
    __syncthreads();
#pragma unroll
    for (int d = 1; d < CHUNK; d <<= 1) {
        unsigned x = (t >= d) ? sh[t - d] : 0u;
        __syncthreads();
        sh[t] += x;
        __syncthreads();
    }
    g_local[bin] = sh[t] - v;            // exclusive within chunk
    if (t == CHUNK - 1) g_partial[blockIdx.x] = sh[t];

    // decoupled last-block global scan of the 256 partials
    __threadfence();
    if (t == 0)
        is_last = (atomicAdd(&g_arrive, 1u) == NCHUNKS - 1);
    __syncthreads();
    if (is_last) {
        // 128 threads, 2 partials each
        unsigned p0 = g_partial[2 * t];
        unsigned p1 = g_partial[2 * t + 1];
        unsigned s = p0 + p1;
        sh[t] = s;
        __syncthreads();
#pragma unroll
        for (int d = 1; d < CHUNK; d <<= 1) {
            unsigned x = (t >= d) ? sh[t - d] : 0u;
            __syncthreads();
            sh[t] += x;
            __syncthreads();
        }
        unsigned base = sh[t] - s;
        g_base[2 * t]     = base;
        g_base[2 * t + 1] = base + p0;
        if (t == 0) g_arrive = 0;        // reset ticket for next call
    }
}

// atomic-free scatter: pos = base[chunk] + local[bin] + rank
__global__ void scatter_kernel(const float* __restrict__ pts, int n) {
    int i = blockIdx.x * blockDim.x + threadIdx.x;
    if (i >= n) return;
    unsigned br = g_binrank[i];
    unsigned bin = br & 0x7FFFu;
    unsigned pos = g_base[bin >> 7] + g_local[bin] + (br >> 15);
    float x = pts[3 * i + 0], y = pts[3 * i + 1], z = pts[3 * i + 2];
    g_sorted[pos] = make_float4(x, y, z, __int_as_float(i));
}

__device__ __forceinline__ float2 lerp2(float2 a, float2 b, float t) {
    float2 r;
    r.x = a.x + t * (b.x - a.x);
    r.y = a.y + t * (b.y - a.y);
    return r;
}

// issue the 8 corner gathers + weights for level `lv` into buffer `buf`.
// LDOP = __ldg (allocate L1) for coarse/mid, __ldcg (L2-only) for fine.
#define LOAD_LEVEL_OP(lv, buf, LDOP)                                         \
    do {                                                                     \
        float rh = c_resh[lv];                                               \
        float sx = ax * rh, sy = ay * rh, sz = az * rh;                      \
        int ixi = __float2int_rd(sx);                                        \
        int iyi = __float2int_rd(sy);                                        \
        int izi = __float2int_rd(sz);                                        \
        wbx[buf] = sx - (float)ixi;                                          \
        wby[buf] = sy - (float)iyi;                                          \
        wbz[buf] = sz - (float)izi;                                          \
        unsigned hx0 = (unsigned)ixi * P0, hx1 = hx0 + P0;                   \
        unsigned hy0 = (unsigned)iyi * P1, hy1 = hy0 + P1;                   \
        unsigned hz0 = (unsigned)izi * P2, hz1 = hz0 + P2;                   \
        const float2* t = tables + (size_t)(lv) * TABLE_SZ;                  \
        cbuf[buf][0] = LDOP(t + ((hx0 ^ hy0 ^ hz0) & TMASK));                \
        cbuf[buf][1] = LDOP(t + ((hx0 ^ hy0 ^ hz1) & TMASK));                \
        cbuf[buf][2] = LDOP(t + ((hx0 ^ hy1 ^ hz0) & TMASK));                \
        cbuf[buf][3] = LDOP(t + ((hx0 ^ hy1 ^ hz1) & TMASK));                \
        cbuf[buf][4] = LDOP(t + ((hx1 ^ hy0 ^ hz0) & TMASK));                \
        cbuf[buf][5] = LDOP(t + ((hx1 ^ hy0 ^ hz1) & TMASK));                \
        cbuf[buf][6] = LDOP(t + ((hx1 ^ hy1 ^ hz0) & TMASK));                \
        cbuf[buf][7] = LDOP(t + ((hx1 ^ hy1 ^ hz1) & TMASK));                \
    } while (0)

__global__ __launch_bounds__(256, 4)
void hashgrid_kernel(const float2* __restrict__ tables,
                     float4* __restrict__ out,   // [n, 8] float4
                     int n)
{
    // SM-affinity remap: blocks sharing an SM (bid % 148) get consecutive
    // sorted segments -> each SM's corner working set is one Morton region.
    int G = gridDim.x;
    int b = blockIdx.x;
    int g = b % NSM;
    int i = b / NSM;
    int q = G / NSM, r = G % NSM;
    int seg = g * q + min(g, r) + i;

    int s = seg * (int)blockDim.x + threadIdx.x;
    if (s >= n) return;

    float4 f = g_sorted[s];
    int orig = __float_as_int(f.w);

    float ax = f.x + 1.0f;
    float ay = f.y + 1.0f;
    float az = f.z + 1.0f;

    const unsigned P0 = 73856093u, P1 = 19349663u, P2 = 83492791u;

    float2 cbuf[2][8];
    float wbx[2], wby[2], wbz[2];

    LOAD_LEVEL_OP(0, 0, __ldg);   // prologue: level 0 in flight

    float4* o = out + (size_t)orig * (N_LEVELS / 2);
    float4 acc;

#pragma unroll
    for (int l = 0; l < N_LEVELS; l++) {
        const int cur = l & 1;
        const int nxt = cur ^ 1;

        // issue next level's gathers BEFORE consuming this level's corners.
        // fine levels (>= CG_FROM): L2-only loads, preserve L1 for mid levels.
        if (l + 1 < N_LEVELS) {
            if (l + 1 >= CG_FROM) LOAD_LEVEL_OP(l + 1, nxt, __ldcg);
            else                  LOAD_LEVEL_OP(l + 1, nxt, __ldg);
        }

        float wx = wbx[cur], wy = wby[cur], wz = wbz[cur];
        float2 c00 = lerp2(cbuf[cur][0], cbuf[cur][1], wz);
        float2 c01 = lerp2(cbuf[cur][2], cbuf[cur][3], wz);
        float2 c10 = lerp2(cbuf[cur][4], cbuf[cur][5], wz);
        float2 c11 = lerp2(cbuf[cur][6], cbuf[cur][7], wz);
        float2 c0  = lerp2(c00, c01, wy);
        float2 c1  = lerp2(c10, c11, wy);
        float2 r2  = lerp2(c0, c1, wx);

        if ((l & 1) == 0) {
            acc.x = r2.x; acc.y = r2.y;
        } else {
            acc.z = r2.x; acc.w = r2.y;
            o[l >> 1] = acc;
        }
    }
}

extern "C" void kernel_launch(void* const* d_in, const int* in_sizes, int n_in,
                              void* d_out, int out_size)
{
    const float*  pts    = (const float*)d_in[0];   // [n, 3]
    const float2* tables = (const float2*)d_in[1];  // [16, 2^19] float2
    float4*       out    = (float4*)d_out;          // [n, 8] float4

    int n = in_sizes[0] / 3;
    if (n > MAXPTS) n = MAXPTS;

    int T = 256;
    int gp = (n + T - 1) / T;

    count_kernel<<<gp, T>>>(pts, n);
    scan_kernel<<<NCHUNKS, CHUNK>>>();
    scatter_kernel<<<gp, T>>>(pts, n);
    hashgrid_kernel<<<gp, T>>>(tables, out, n);
}